// round 3
// baseline (speedup 1.0000x reference)
#include <cuda_runtime.h>
#include <math.h>

#define Bn 4
#define Cn 64
#define Hn 128
#define Wn 128
#define On 64

// Scratch (device globals -- no allocations allowed)
__device__ float g_offset[Bn * 18 * Hn * Wn];   // [B,18,H,W]
__device__ float g_mask[Bn * 9 * Hn * Wn];      // [B,9,H,W] (post-sigmoid)
__device__ float g_wT[9 * Cn * On];             // [k][c][o]

// ---------------------------------------------------------------------------
// Kernel W: transpose deform_w [O][C][3][3] -> [k][c][o]
// ---------------------------------------------------------------------------
__global__ void transpose_w_kernel(const float* __restrict__ dw) {
    int idx = blockIdx.x * blockDim.x + threadIdx.x;
    if (idx >= On * Cn * 9) return;
    int k = idx % 9;
    int c = (idx / 9) % Cn;
    int o = idx / (9 * Cn);
    g_wT[(k * Cn + c) * On + o] = dw[idx];
}

// ---------------------------------------------------------------------------
// Kernel A: fused offset conv (18ch) + mask conv (9ch) + sigmoid
// One block per (b,h) row; 128 threads = one pixel each.
// 27 accumulators per thread (padded to 28 for float4 weight loads).
// Weights staged in SMEM as [c][tap][28].
// ---------------------------------------------------------------------------
__global__ __launch_bounds__(128) void offset_mask_kernel(
    const float* __restrict__ x,
    const float* __restrict__ offset_w,
    const float* __restrict__ offset_b,
    const float* __restrict__ mask_w,
    const float* __restrict__ mask_b)
{
    extern __shared__ float sm[];
    float* wsA = sm;                 // 64*9*28 floats
    float* xs  = sm + Cn * 9 * 28;   // 3 rows * 132 cols (halo cols 0 and 129)

    const int w = threadIdx.x;
    const int h = blockIdx.x;
    const int b = blockIdx.y;

    // Stage weights: offset_w [j][c][tap] (j<18), mask_w [j-18][c][tap]
    for (int s = w; s < 18 * Cn * 9; s += 128) {
        int tap = s % 9;
        int c = (s / 9) % Cn;
        int j = s / (9 * Cn);
        wsA[(c * 9 + tap) * 28 + j] = offset_w[s];
    }
    for (int s = w; s < 9 * Cn * 9; s += 128) {
        int tap = s % 9;
        int c = (s / 9) % Cn;
        int j = 18 + s / (9 * Cn);
        wsA[(c * 9 + tap) * 28 + j] = mask_w[s];
    }
    for (int s = w; s < Cn * 9; s += 128) wsA[s * 28 + 27] = 0.f;
    // halo columns are always out-of-range (PAD=1) -> zero, set once
    if (w < 3) { xs[w * 132 + 0] = 0.f; xs[w * 132 + 129] = 0.f; }

    float acc[28];
#pragma unroll
    for (int j = 0; j < 28; ++j) acc[j] = 0.f;

    for (int c = 0; c < Cn; ++c) {
        __syncthreads();
#pragma unroll
        for (int r = 0; r < 3; ++r) {
            int y = h - 1 + r;
            float v = 0.f;
            if (y >= 0 && y < Hn) v = x[((b * Cn + c) * Hn + y) * Wn + w];
            xs[r * 132 + w + 1] = v;
        }
        __syncthreads();
#pragma unroll
        for (int tap = 0; tap < 9; ++tap) {
            float xv = xs[(tap / 3) * 132 + w + (tap % 3)];
            const float4* wp =
                reinterpret_cast<const float4*>(wsA + (c * 9 + tap) * 28);
#pragma unroll
            for (int j4 = 0; j4 < 7; ++j4) {
                float4 ww = wp[j4];
                acc[j4 * 4 + 0] += ww.x * xv;
                acc[j4 * 4 + 1] += ww.y * xv;
                acc[j4 * 4 + 2] += ww.z * xv;
                acc[j4 * 4 + 3] += ww.w * xv;
            }
        }
    }

    const int p = h * Wn + w;
#pragma unroll
    for (int j = 0; j < 18; ++j)
        g_offset[(b * 18 + j) * Hn * Wn + p] = acc[j] + __ldg(offset_b + j);
#pragma unroll
    for (int j = 0; j < 9; ++j) {
        float v = acc[18 + j] + __ldg(mask_b + j);
        g_mask[(b * 9 + j) * Hn * Wn + p] = 1.f / (1.f + __expf(-v));
    }
}

// ---------------------------------------------------------------------------
// Kernel B: deformable conv.
// One block per (b,h) row; 128 threads = one pixel each; 64 fp32 accumulators.
// Per k: stage weight slice [c][o] (16KB) in SMEM, bilinear-sample each channel,
// broadcast-FMA into 64 accumulators.
// ---------------------------------------------------------------------------
__global__ __launch_bounds__(128, 4) void deform_kernel(
    const float* __restrict__ x,
    const float* __restrict__ deform_b,
    float* __restrict__ out)
{
    __shared__ float ws[Cn * On];   // 16 KB

    const int w = threadIdx.x;
    const int h = blockIdx.x;
    const int b = blockIdx.y;

    float acc[On];
#pragma unroll
    for (int o = 0; o < On; ++o) acc[o] = 0.f;

    const float* xb = x + (size_t)b * Cn * Hn * Wn;
    const int p = h * Wn + w;

    for (int k = 0; k < 9; ++k) {
        // stage weight slice for this k
        __syncthreads();
        {
            const float4* src =
                reinterpret_cast<const float4*>(g_wT + k * Cn * On);
            float4* dst = reinterpret_cast<float4*>(ws);
            for (int s = w; s < Cn * On / 4; s += 128) dst[s] = src[s];
        }
        __syncthreads();

        float dy = g_offset[(b * 18 + 2 * k) * Hn * Wn + p];
        float dx = g_offset[(b * 18 + 2 * k + 1) * Hn * Wn + p];
        float m  = g_mask[(b * 9 + k) * Hn * Wn + p];

        float py = dy + (float)(k / 3 + h - 1);
        float px = dx + (float)(k % 3 + w - 1);
        float y0f = floorf(py), x0f = floorf(px);
        float fy = py - y0f, fx = px - x0f;
        int y0 = (int)y0f, x0 = (int)x0f;
        int y1 = y0 + 1, x1 = x0 + 1;
        float wy0 = 1.f - fy, wx0 = 1.f - fx;
        float w00 = wy0 * wx0 * m;
        float w01 = wy0 * fx  * m;
        float w10 = fy  * wx0 * m;
        float w11 = fy  * fx  * m;
        bool vy0 = (y0 >= 0) && (y0 < Hn);
        bool vy1 = (y1 >= 0) && (y1 < Hn);
        bool vx0 = (x0 >= 0) && (x0 < Wn);
        bool vx1 = (x1 >= 0) && (x1 < Wn);
        if (!(vy0 && vx0)) w00 = 0.f;
        if (!(vy0 && vx1)) w01 = 0.f;
        if (!(vy1 && vx0)) w10 = 0.f;
        if (!(vy1 && vx1)) w11 = 0.f;
        int y0c = min(max(y0, 0), Hn - 1), y1c = min(max(y1, 0), Hn - 1);
        int x0c = min(max(x0, 0), Wn - 1), x1c = min(max(x1, 0), Wn - 1);
        int i00 = y0c * Wn + x0c, i01 = y0c * Wn + x1c;
        int i10 = y1c * Wn + x0c, i11 = y1c * Wn + x1c;

#pragma unroll 2
        for (int c = 0; c < Cn; ++c) {
            const float* xc = xb + c * (Hn * Wn);
            float v = w00 * __ldg(xc + i00) + w01 * __ldg(xc + i01)
                    + w10 * __ldg(xc + i10) + w11 * __ldg(xc + i11);
            const float4* wp = reinterpret_cast<const float4*>(ws + c * On);
#pragma unroll
            for (int o4 = 0; o4 < 16; ++o4) {
                float4 ww = wp[o4];
                acc[o4 * 4 + 0] += ww.x * v;
                acc[o4 * 4 + 1] += ww.y * v;
                acc[o4 * 4 + 2] += ww.z * v;
                acc[o4 * 4 + 3] += ww.w * v;
            }
        }
    }

#pragma unroll
    for (int o = 0; o < On; ++o)
        out[((size_t)(b * On + o)) * (Hn * Wn) + p] = acc[o] + __ldg(deform_b + o);
}

// ---------------------------------------------------------------------------
extern "C" void kernel_launch(void* const* d_in, const int* in_sizes, int n_in,
                              void* d_out, int out_size) {
    const float* x        = (const float*)d_in[0];
    const float* offset_w = (const float*)d_in[1];
    const float* offset_b = (const float*)d_in[2];
    const float* mask_w   = (const float*)d_in[3];
    const float* mask_b   = (const float*)d_in[4];
    const float* deform_w = (const float*)d_in[5];
    const float* deform_b = (const float*)d_in[6];
    float* out = (float*)d_out;

    transpose_w_kernel<<<(On * Cn * 9 + 255) / 256, 256>>>(deform_w);

    int smemA = (Cn * 9 * 28 + 3 * 132) * (int)sizeof(float);  // ~66 KB
    cudaFuncSetAttribute(offset_mask_kernel,
                         cudaFuncAttributeMaxDynamicSharedMemorySize, smemA);

    dim3 grid(Hn, Bn);
    offset_mask_kernel<<<grid, 128, smemA>>>(x, offset_w, offset_b, mask_w, mask_b);
    deform_kernel<<<grid, 128>>>(x, deform_b, out);
}

// round 4
// speedup vs baseline: 1.4155x; 1.4155x over previous
#include <cuda_runtime.h>
#include <math.h>

#define Bn 4
#define Cn 64
#define Hn 128
#define Wn 128
#define On 64
#define HW (Hn * Wn)

typedef unsigned long long ull;

// Scratch (device globals -- no allocations allowed)
__device__ float g_offset[Bn * 18 * HW];   // [B,18,H,W]
__device__ float g_mask[Bn * 9 * HW];      // [B,9,H,W] (post-sigmoid)
__device__ float g_wT[9 * Cn * On];        // [k][c][o]

// ---------------------------------------------------------------------------
// f32x2 packed helpers (Blackwell FFMA2 path -- only reachable via PTX)
// ---------------------------------------------------------------------------
__device__ __forceinline__ ull pack2(float a, float b) {
    ull r;
    asm("mov.b64 %0, {%1, %2};" : "=l"(r) : "f"(a), "f"(b));
    return r;
}
__device__ __forceinline__ float2 unpack2(ull v) {
    float2 r;
    asm("mov.b64 {%0, %1}, %2;" : "=f"(r.x), "=f"(r.y) : "l"(v));
    return r;
}
__device__ __forceinline__ void ffma2(ull& d, ull a, ull b) {
    asm("fma.rn.f32x2 %0, %1, %2, %0;" : "+l"(d) : "l"(a), "l"(b));
}

// ---------------------------------------------------------------------------
// Kernel A: fused offset conv (18ch) + mask conv (9ch) + sigmoid, f32x2 MACs.
// Also transposes deform_w [O][C][3][3] -> g_wT [k][c][o] (1 elem/thread).
// One block per (b,h) row; 128 threads = one pixel each.
// acc: 14 f32x2 pairs (28 slots, ch 27 is zero pad).
// ---------------------------------------------------------------------------
__global__ __launch_bounds__(128) void offset_mask_kernel(
    const float* __restrict__ x,
    const float* __restrict__ offset_w,
    const float* __restrict__ offset_b,
    const float* __restrict__ mask_w,
    const float* __restrict__ mask_b,
    const float* __restrict__ deform_w)
{
    extern __shared__ float sm[];
    float* wsA = sm;                 // 64*9*28 floats
    float* xs  = sm + Cn * 9 * 28;   // 3 rows * 132 cols (halo cols 0 and 129)

    const int w = threadIdx.x;
    const int h = blockIdx.x;
    const int b = blockIdx.y;

    // Fold-in: transpose deform_w -> g_wT, one element per (block,thread)
    {
        int idx = (b * gridDim.x + h) * 128 + w;
        if (idx < On * Cn * 9) {
            int k = idx % 9;
            int c = (idx / 9) % Cn;
            int o = idx / (9 * Cn);
            g_wT[(k * Cn + c) * On + o] = deform_w[idx];
        }
    }

    // Stage weights: offset_w [j][c][tap] (j<18), mask_w [j-18][c][tap]
    for (int s = w; s < 18 * Cn * 9; s += 128) {
        int tap = s % 9;
        int c = (s / 9) % Cn;
        int j = s / (9 * Cn);
        wsA[(c * 9 + tap) * 28 + j] = offset_w[s];
    }
    for (int s = w; s < 9 * Cn * 9; s += 128) {
        int tap = s % 9;
        int c = (s / 9) % Cn;
        int j = 18 + s / (9 * Cn);
        wsA[(c * 9 + tap) * 28 + j] = mask_w[s];
    }
    for (int s = w; s < Cn * 9; s += 128) wsA[s * 28 + 27] = 0.f;
    if (w < 3) { xs[w * 132 + 0] = 0.f; xs[w * 132 + 129] = 0.f; }

    ull acc2[14];
#pragma unroll
    for (int j = 0; j < 14; ++j) acc2[j] = 0ull;

    for (int c = 0; c < Cn; ++c) {
        __syncthreads();
#pragma unroll
        for (int r = 0; r < 3; ++r) {
            int y = h - 1 + r;
            float v = 0.f;
            if (y >= 0 && y < Hn) v = x[((b * Cn + c) * Hn + y) * Wn + w];
            xs[r * 132 + w + 1] = v;
        }
        __syncthreads();
#pragma unroll
        for (int tap = 0; tap < 9; ++tap) {
            float xv = xs[(tap / 3) * 132 + w + (tap % 3)];
            ull xv2 = pack2(xv, xv);
            const ulonglong2* wp =
                reinterpret_cast<const ulonglong2*>(wsA + (c * 9 + tap) * 28);
#pragma unroll
            for (int j2 = 0; j2 < 7; ++j2) {
                ulonglong2 ww = wp[j2];          // broadcast LDS.128
                ffma2(acc2[j2 * 2 + 0], ww.x, xv2);
                ffma2(acc2[j2 * 2 + 1], ww.y, xv2);
            }
        }
    }

    const int p = h * Wn + w;
#pragma unroll
    for (int jp = 0; jp < 14; ++jp) {
        float2 f = unpack2(acc2[jp]);
        int ch0 = 2 * jp, ch1 = 2 * jp + 1;
        // ch0
        if (ch0 < 18) {
            g_offset[(b * 18 + ch0) * HW + p] = f.x + __ldg(offset_b + ch0);
        } else {
            float v = f.x + __ldg(mask_b + (ch0 - 18));
            g_mask[(b * 9 + (ch0 - 18)) * HW + p] = 1.f / (1.f + __expf(-v));
        }
        // ch1 (27 is pad -> skip)
        if (ch1 < 18) {
            g_offset[(b * 18 + ch1) * HW + p] = f.y + __ldg(offset_b + ch1);
        } else if (ch1 < 27) {
            float v = f.y + __ldg(mask_b + (ch1 - 18));
            g_mask[(b * 9 + (ch1 - 18)) * HW + p] = 1.f / (1.f + __expf(-v));
        }
    }
}

// ---------------------------------------------------------------------------
// Kernel B: deformable conv, two-phase per k.
//   Phase 1: 128 threads = 128 pixels; bilinear-sample all 64 channels into
//            vsm[c][128].
//   Phase 2: warp = one o-group of 16 channels (broadcast weight LDS);
//            thread handles 4 pixels x 16 o = 64 accumulators as 32 f32x2.
// ---------------------------------------------------------------------------
__global__ __launch_bounds__(128) void deform_kernel(
    const float* __restrict__ x,
    const float* __restrict__ deform_b,
    float* __restrict__ out)
{
    extern __shared__ float sm[];
    float* vsm = sm;                 // 64 * 128 floats (32 KB)
    float* ws  = sm + Cn * 128;      // 64 * 64 floats (16 KB)

    const int tid = threadIdx.x;
    const int pg  = tid & 31;        // pixel group: pixels pg*4 .. pg*4+3
    const int og  = tid >> 5;        // o group: channels og*16 .. og*16+15
    const int h = blockIdx.x;
    const int b = blockIdx.y;

    ull acc2[32];                    // [pixel 0..3][o-pair 0..7]
#pragma unroll
    for (int i = 0; i < 32; ++i) acc2[i] = 0ull;

    const float* xb = x + (size_t)b * Cn * HW;
    const int p = h * Wn + tid;      // phase-1 pixel for this thread

    for (int k = 0; k < 9; ++k) {
        __syncthreads();             // protect vsm/ws from previous phase 2

        // stage weight slice for this k
        {
            const float4* src = reinterpret_cast<const float4*>(g_wT + k * Cn * On);
            float4* dst = reinterpret_cast<float4*>(ws);
            for (int s = tid; s < Cn * On / 4; s += 128) dst[s] = src[s];
        }

        // bilinear setup for pixel `tid` of row h
        float dy = g_offset[(b * 18 + 2 * k) * HW + p];
        float dx = g_offset[(b * 18 + 2 * k + 1) * HW + p];
        float m  = g_mask[(b * 9 + k) * HW + p];

        float py = dy + (float)(k / 3 + h - 1);
        float px = dx + (float)(k % 3 + tid - 1);
        float y0f = floorf(py), x0f = floorf(px);
        float fy = py - y0f, fx = px - x0f;
        int y0 = (int)y0f, x0 = (int)x0f;
        int y1 = y0 + 1, x1 = x0 + 1;
        float wy0 = 1.f - fy, wx0 = 1.f - fx;
        float w00 = wy0 * wx0 * m;
        float w01 = wy0 * fx  * m;
        float w10 = fy  * wx0 * m;
        float w11 = fy  * fx  * m;
        bool vy0 = (y0 >= 0) && (y0 < Hn);
        bool vy1 = (y1 >= 0) && (y1 < Hn);
        bool vx0 = (x0 >= 0) && (x0 < Wn);
        bool vx1 = (x1 >= 0) && (x1 < Wn);
        if (!(vy0 && vx0)) w00 = 0.f;
        if (!(vy0 && vx1)) w01 = 0.f;
        if (!(vy1 && vx0)) w10 = 0.f;
        if (!(vy1 && vx1)) w11 = 0.f;
        int y0c = min(max(y0, 0), Hn - 1), y1c = min(max(y1, 0), Hn - 1);
        int x0c = min(max(x0, 0), Wn - 1), x1c = min(max(x1, 0), Wn - 1);
        int i00 = y0c * Wn + x0c, i01 = y0c * Wn + x1c;
        int i10 = y1c * Wn + x0c, i11 = y1c * Wn + x1c;

        // Phase 1: fill vsm[c][tid] for all channels
#pragma unroll 4
        for (int c = 0; c < Cn; ++c) {
            const float* xc = xb + c * HW;
            float v = w00 * __ldg(xc + i00) + w01 * __ldg(xc + i01)
                    + w10 * __ldg(xc + i10) + w11 * __ldg(xc + i11);
            vsm[c * 128 + tid] = v;
        }
        __syncthreads();

        // Phase 2: accumulate. Warp-uniform weight reads (broadcast LDS).
        for (int c = 0; c < Cn; ++c) {
            float4 v4 = *reinterpret_cast<const float4*>(vsm + c * 128 + pg * 4);
            ull vv0 = pack2(v4.x, v4.x);
            ull vv1 = pack2(v4.y, v4.y);
            ull vv2 = pack2(v4.z, v4.z);
            ull vv3 = pack2(v4.w, v4.w);
            const ulonglong2* wp =
                reinterpret_cast<const ulonglong2*>(ws + c * On + og * 16);
#pragma unroll
            for (int j2 = 0; j2 < 4; ++j2) {
                ulonglong2 ww = wp[j2];          // broadcast LDS.128
#pragma unroll
                for (int half = 0; half < 2; ++half) {
                    ull wv = half ? ww.y : ww.x;
                    int j = j2 * 2 + half;
                    ffma2(acc2[0 * 8 + j], wv, vv0);
                    ffma2(acc2[1 * 8 + j], wv, vv1);
                    ffma2(acc2[2 * 8 + j], wv, vv2);
                    ffma2(acc2[3 * 8 + j], wv, vv3);
                }
            }
        }
    }

    // Epilogue: unpack, add bias, coalesced float4 stores (4 pixels per store)
    const int pbase = h * Wn + pg * 4;
#pragma unroll
    for (int j = 0; j < 8; ++j) {
        int o = og * 16 + 2 * j;
        float2 f0 = unpack2(acc2[0 * 8 + j]);
        float2 f1 = unpack2(acc2[1 * 8 + j]);
        float2 f2 = unpack2(acc2[2 * 8 + j]);
        float2 f3 = unpack2(acc2[3 * 8 + j]);
        float b0 = __ldg(deform_b + o);
        float b1 = __ldg(deform_b + o + 1);
        float4 lo = make_float4(f0.x + b0, f1.x + b0, f2.x + b0, f3.x + b0);
        float4 hi = make_float4(f0.y + b1, f1.y + b1, f2.y + b1, f3.y + b1);
        *reinterpret_cast<float4*>(out + ((size_t)(b * On + o)) * HW + pbase) = lo;
        *reinterpret_cast<float4*>(out + ((size_t)(b * On + o + 1)) * HW + pbase) = hi;
    }
}

// ---------------------------------------------------------------------------
extern "C" void kernel_launch(void* const* d_in, const int* in_sizes, int n_in,
                              void* d_out, int out_size) {
    const float* x        = (const float*)d_in[0];
    const float* offset_w = (const float*)d_in[1];
    const float* offset_b = (const float*)d_in[2];
    const float* mask_w   = (const float*)d_in[3];
    const float* mask_b   = (const float*)d_in[4];
    const float* deform_w = (const float*)d_in[5];
    const float* deform_b = (const float*)d_in[6];
    float* out = (float*)d_out;

    static int configured = 0;
    int smemA = (Cn * 9 * 28 + 3 * 132) * (int)sizeof(float);   // ~66 KB
    int smemB = (Cn * 128 + Cn * On) * (int)sizeof(float);      // 48 KB
    if (!configured) {
        cudaFuncSetAttribute(offset_mask_kernel,
                             cudaFuncAttributeMaxDynamicSharedMemorySize, smemA);
        cudaFuncSetAttribute(deform_kernel,
                             cudaFuncAttributeMaxDynamicSharedMemorySize, smemB);
        configured = 1;
    }

    dim3 grid(Hn, Bn);
    offset_mask_kernel<<<grid, 128, smemA>>>(x, offset_w, offset_b,
                                             mask_w, mask_b, deform_w);
    deform_kernel<<<grid, 128, smemB>>>(x, deform_b, out);
}

// round 7
// speedup vs baseline: 2.0697x; 1.4621x over previous
#include <cuda_runtime.h>
#include <cuda_bf16.h>
#include <stdint.h>
#include <math.h>

#define Bn 4
#define Cn 64
#define Hn 128
#define Wn 128
#define On 64
#define HW (Hn * Wn)

typedef unsigned long long ull;

// Scratch (device globals -- no allocations allowed)
__device__ float g_offset[Bn * 18 * HW];              // [B,18,H,W]
__device__ float g_mask[Bn * 9 * HW];                 // [B,9,H,W] (post-sigmoid)
__device__ __align__(16) uint32_t g_wBh[9 * 2048];    // per-k B tile [o][c] bf16-hi, sw128
__device__ __align__(16) uint32_t g_wBl[9 * 2048];    // per-k B tile [o][c] bf16-lo, sw128

// ---------------------------------------------------------------------------
// helpers
// ---------------------------------------------------------------------------
__device__ __forceinline__ ull pack2(float a, float b) {
    ull r; asm("mov.b64 %0, {%1, %2};" : "=l"(r) : "f"(a), "f"(b)); return r;
}
__device__ __forceinline__ float2 unpack2(ull v) {
    float2 r; asm("mov.b64 {%0, %1}, %2;" : "=f"(r.x), "=f"(r.y) : "l"(v)); return r;
}
__device__ __forceinline__ void ffma2(ull& d, ull a, ull b) {
    asm("fma.rn.f32x2 %0, %1, %2, %0;" : "+l"(d) : "l"(a), "l"(b));
}
// pack (lo,hi) floats into bf16x2 word (second arg goes to high half)
__device__ __forceinline__ uint32_t cvt_bf16x2(float lo, float hi) {
    uint32_t r;
    asm("cvt.rn.satfinite.bf16x2.f32 %0, %1, %2;" : "=r"(r) : "f"(hi), "f"(lo));
    return r;
}
__device__ __forceinline__ uint32_t smem_u32(const void* p) {
    uint32_t a;
    asm("{ .reg .u64 t; cvta.to.shared.u64 t, %1; cvt.u32.u64 %0, t; }"
        : "=r"(a) : "l"(p));
    return a;
}
__device__ __forceinline__ uint32_t sw128(uint32_t off) {
    return off ^ ((off >> 3) & 0x70);
}
__device__ __forceinline__ uint32_t lds32(uint32_t addr) {
    uint32_t v; asm volatile("ld.shared.b32 %0, [%1];" : "=r"(v) : "r"(addr));
    return v;
}
__device__ __forceinline__ void sts32(uint32_t addr, uint32_t v) {
    asm volatile("st.shared.b32 [%0], %1;" :: "r"(addr), "r"(v) : "memory");
}
// m16n8k16 row.col bf16 -> fp32
__device__ __forceinline__ void mma16816(float* d, const uint32_t* a,
                                         const uint32_t* b) {
    asm volatile(
        "mma.sync.aligned.m16n8k16.row.col.f32.bf16.bf16.f32 "
        "{%0,%1,%2,%3}, {%4,%5,%6,%7}, {%8,%9}, {%0,%1,%2,%3};"
        : "+f"(d[0]), "+f"(d[1]), "+f"(d[2]), "+f"(d[3])
        : "r"(a[0]), "r"(a[1]), "r"(a[2]), "r"(a[3]), "r"(b[0]), "r"(b[1]));
}

// ---------------------------------------------------------------------------
// Kernel P: split deform_w into bf16 hi/lo B tiles [k][o(row)][c(col)], sw128.
// ---------------------------------------------------------------------------
__global__ void prep_w_kernel(const float* __restrict__ dw) {
    int idx = blockIdx.x * blockDim.x + threadIdx.x;
    if (idx >= 9 * 64 * 32) return;
    int cp = idx & 31;            // c pair
    int o  = (idx >> 5) & 63;
    int k  = idx >> 11;           // 0..8
    int c0 = cp * 2;
    float w0 = dw[(o * Cn + c0) * 9 + k];
    float w1 = dw[(o * Cn + c0 + 1) * 9 + k];
    uint32_t hw = cvt_bf16x2(w0, w1);
    float h0 = __uint_as_float(hw << 16);
    float h1 = __uint_as_float(hw & 0xFFFF0000u);
    uint32_t lw = cvt_bf16x2(w0 - h0, w1 - h1);
    uint32_t byte_off = sw128((uint32_t)(o * 128 + cp * 4));
    g_wBh[k * 2048 + byte_off / 4] = hw;
    g_wBl[k * 2048 + byte_off / 4] = lw;
}

// ---------------------------------------------------------------------------
// Kernel A: fused offset conv (18ch) + mask conv (9ch) + sigmoid, f32x2 MACs.
// 256 threads = TWO rows per block.
// ---------------------------------------------------------------------------
__global__ __launch_bounds__(256) void offset_mask_kernel(
    const float* __restrict__ x,
    const float* __restrict__ offset_w,
    const float* __restrict__ offset_b,
    const float* __restrict__ mask_w,
    const float* __restrict__ mask_b)
{
    extern __shared__ float wsA[];   // [c][tap][28]

    const int tid = threadIdx.x;
    const int w = tid & 127;
    const int h = 2 * blockIdx.x + (tid >> 7);
    const int b = blockIdx.y;

    for (int s = tid; s < 18 * Cn * 9; s += 256) {
        int tap = s % 9;
        int c = (s / 9) % Cn;
        int j = s / (9 * Cn);
        wsA[(c * 9 + tap) * 28 + j] = offset_w[s];
    }
    for (int s = tid; s < 9 * Cn * 9; s += 256) {
        int tap = s % 9;
        int c = (s / 9) % Cn;
        int j = 18 + s / (9 * Cn);
        wsA[(c * 9 + tap) * 28 + j] = mask_w[s];
    }
    for (int s = tid; s < Cn * 9; s += 256) wsA[s * 28 + 27] = 0.f;
    __syncthreads();

    ull acc2[14];
#pragma unroll
    for (int j = 0; j < 14; ++j) acc2[j] = 0ull;

    const bool ymv[3] = { h - 1 >= 0, true, h + 1 < Hn };
    const bool xmv[3] = { w - 1 >= 0, true, w + 1 < Wn };
    const float* base0 = x + ((size_t)(b * Cn) * Hn + h) * Wn + w;

    for (int c = 0; c < Cn; ++c) {
        const float* base = base0 + c * HW;
        float xv[9];
#pragma unroll
        for (int r = 0; r < 3; ++r)
#pragma unroll
            for (int dc = 0; dc < 3; ++dc) {
                float v = 0.f;
                if (ymv[r] && xmv[dc]) v = __ldg(base + (r - 1) * Wn + (dc - 1));
                xv[r * 3 + dc] = v;
            }
#pragma unroll
        for (int tap = 0; tap < 9; ++tap) {
            ull xv2 = pack2(xv[tap], xv[tap]);
            const ulonglong2* wp =
                reinterpret_cast<const ulonglong2*>(wsA + (c * 9 + tap) * 28);
#pragma unroll
            for (int j2 = 0; j2 < 7; ++j2) {
                ulonglong2 ww = wp[j2];          // broadcast LDS.128
                ffma2(acc2[j2 * 2 + 0], ww.x, xv2);
                ffma2(acc2[j2 * 2 + 1], ww.y, xv2);
            }
        }
    }

    const int p = h * Wn + w;
#pragma unroll
    for (int jp = 0; jp < 14; ++jp) {
        float2 f = unpack2(acc2[jp]);
        int ch0 = 2 * jp, ch1 = 2 * jp + 1;
        if (ch0 < 18) {
            g_offset[(b * 18 + ch0) * HW + p] = f.x + __ldg(offset_b + ch0);
        } else {
            float v = f.x + __ldg(mask_b + (ch0 - 18));
            g_mask[(b * 9 + (ch0 - 18)) * HW + p] = 1.f / (1.f + __expf(-v));
        }
        if (ch1 < 18) {
            g_offset[(b * 18 + ch1) * HW + p] = f.y + __ldg(offset_b + ch1);
        } else if (ch1 < 27) {
            float v = f.y + __ldg(mask_b + (ch1 - 18));
            g_mask[(b * 9 + (ch1 - 18)) * HW + p] = 1.f / (1.f + __expf(-v));
        }
    }
}

// ---------------------------------------------------------------------------
// Kernel B: deformable conv via mma.sync.m16n8k16 bf16 split-precision.
// Block = one (b,h) row: M=128 px, N=64 out, K=576 (9 taps x 64c).
// SW128 addressing: element (row, byte col) lives at row*128 + (col ^ swz(row))
// where swz(row) = (row&7)<<4. Column term per k-step lies entirely in bits
// 4-6, so addr = row*128 + lr*4 + ((s*32 + 16*half) ^ swz).
// ---------------------------------------------------------------------------
#define S_AH 0
#define S_AL 16384
#define S_BH 32768
#define S_BL 40960
#define S_TOT 49152

__global__ __launch_bounds__(128) void deform_kernel(
    const float* __restrict__ x,
    const float* __restrict__ deform_b,
    float* __restrict__ out)
{
    extern __shared__ char smem[];
    const uint32_t sb = smem_u32(smem);
    const int tid  = threadIdx.x;
    const int lane = tid & 31;
    const int wrp  = tid >> 5;
    const int h = blockIdx.x;
    const int b = blockIdx.y;

    float d[2][8][4];
#pragma unroll
    for (int mt = 0; mt < 2; ++mt)
#pragma unroll
        for (int nt = 0; nt < 8; ++nt)
#pragma unroll
            for (int i = 0; i < 4; ++i) d[mt][nt][i] = 0.f;

    const float* xb = x + (size_t)b * Cn * HW;
    const int p = h * Wn + tid;

    const int lq = lane >> 2;            // 0..7
    const int lr = lane & 3;             // 0..3
    const uint32_t swz = ((uint32_t)lq << 4);   // rows used always have row%8==lq
    // Unswizzled base: row*128 + lr*4
    uint32_t aBase[2][2];
#pragma unroll
    for (int mt = 0; mt < 2; ++mt)
#pragma unroll
        for (int rh = 0; rh < 2; ++rh) {
            uint32_t row = wrp * 32 + mt * 16 + rh * 8 + lq;
            aBase[mt][rh] = row * 128 + lr * 4;
        }
    const uint32_t bBase0 = (uint32_t)lq * 128 + lr * 4;

    for (int k = 0; k < 9; ++k) {
        __syncthreads();   // previous tap's MMA done reading smem

        // copy pre-swizzled B tiles (8KB hi + 8KB lo)
        {
            const float4* sh = reinterpret_cast<const float4*>(g_wBh + k * 2048);
            const float4* sl = reinterpret_cast<const float4*>(g_wBl + k * 2048);
            float4* dh = reinterpret_cast<float4*>(smem + S_BH);
            float4* dl = reinterpret_cast<float4*>(smem + S_BL);
#pragma unroll
            for (int s = tid; s < 512; s += 128) { dh[s] = sh[s]; dl[s] = sl[s]; }
        }

        // bilinear setup for pixel `tid` of row h
        float dy = g_offset[(b * 18 + 2 * k) * HW + p];
        float dx = g_offset[(b * 18 + 2 * k + 1) * HW + p];
        float m  = g_mask[(b * 9 + k) * HW + p];

        float py = dy + (float)(k / 3 + h - 1);
        float px = dx + (float)(k % 3 + tid - 1);
        float y0f = floorf(py), x0f = floorf(px);
        float fy = py - y0f, fx = px - x0f;
        int y0 = (int)y0f, x0 = (int)x0f;
        int y1 = y0 + 1, x1 = x0 + 1;
        float wy0 = 1.f - fy, wx0 = 1.f - fx;
        float w00 = wy0 * wx0 * m;
        float w01 = wy0 * fx  * m;
        float w10 = fy  * wx0 * m;
        float w11 = fy  * fx  * m;
        bool vy0 = (y0 >= 0) && (y0 < Hn);
        bool vy1 = (y1 >= 0) && (y1 < Hn);
        bool vx0 = (x0 >= 0) && (x0 < Wn);
        bool vx1 = (x1 >= 0) && (x1 < Wn);
        if (!(vy0 && vx0)) w00 = 0.f;
        if (!(vy0 && vx1)) w01 = 0.f;
        if (!(vy1 && vx0)) w10 = 0.f;
        if (!(vy1 && vx1)) w11 = 0.f;
        int y0c = min(max(y0, 0), Hn - 1), y1c = min(max(y1, 0), Hn - 1);
        int x0c = min(max(x0, 0), Wn - 1), x1c = min(max(x1, 0), Wn - 1);
        int i00 = y0c * Wn + x0c, i01 = y0c * Wn + x1c;
        int i10 = y1c * Wn + x0c, i11 = y1c * Wn + x1c;

        // gather + split into A_hi/A_lo (row = pixel tid, col pair cp)
        const uint32_t rowoff = (uint32_t)(tid * 128);
#pragma unroll 4
        for (int cp = 0; cp < 32; ++cp) {
            const float* xc0 = xb + (2 * cp) * HW;
            const float* xc1 = xc0 + HW;
            float v0 = w00 * __ldg(xc0 + i00) + w01 * __ldg(xc0 + i01)
                     + w10 * __ldg(xc0 + i10) + w11 * __ldg(xc0 + i11);
            float v1 = w00 * __ldg(xc1 + i00) + w01 * __ldg(xc1 + i01)
                     + w10 * __ldg(xc1 + i10) + w11 * __ldg(xc1 + i11);
            uint32_t hw = cvt_bf16x2(v0, v1);
            float h0 = __uint_as_float(hw << 16);
            float h1 = __uint_as_float(hw & 0xFFFF0000u);
            uint32_t lw = cvt_bf16x2(v0 - h0, v1 - h1);
            uint32_t off = sw128(rowoff + cp * 4);
            sts32(sb + S_AH + off, hw);
            sts32(sb + S_AL + off, lw);
        }
        __syncthreads();

        // MMA phase: 4 k16-steps
#pragma unroll
        for (int s = 0; s < 4; ++s) {
            const uint32_t c0 = ((uint32_t)(s * 32)) ^ swz;       // k 0..7 half
            const uint32_t c1 = ((uint32_t)(s * 32 + 16)) ^ swz;  // k 8..15 half
            uint32_t ah[2][4], al[2][4];
#pragma unroll
            for (int mt = 0; mt < 2; ++mt) {
                ah[mt][0] = lds32(sb + S_AH + aBase[mt][0] + c0);
                ah[mt][1] = lds32(sb + S_AH + aBase[mt][1] + c0);
                ah[mt][2] = lds32(sb + S_AH + aBase[mt][0] + c1);
                ah[mt][3] = lds32(sb + S_AH + aBase[mt][1] + c1);
                al[mt][0] = lds32(sb + S_AL + aBase[mt][0] + c0);
                al[mt][1] = lds32(sb + S_AL + aBase[mt][1] + c0);
                al[mt][2] = lds32(sb + S_AL + aBase[mt][0] + c1);
                al[mt][3] = lds32(sb + S_AL + aBase[mt][1] + c1);
            }
#pragma unroll
            for (int nt = 0; nt < 8; ++nt) {
                const uint32_t bo = bBase0 + (uint32_t)(nt * 1024);
                uint32_t bh[2], bl[2];
                bh[0] = lds32(sb + S_BH + bo + c0);
                bh[1] = lds32(sb + S_BH + bo + c1);
                bl[0] = lds32(sb + S_BL + bo + c0);
                bl[1] = lds32(sb + S_BL + bo + c1);
#pragma unroll
                for (int mt = 0; mt < 2; ++mt) {
                    mma16816(d[mt][nt], ah[mt], bh);
                    mma16816(d[mt][nt], al[mt], bh);
                    mma16816(d[mt][nt], ah[mt], bl);
                }
            }
        }
    }

    // epilogue: d[mt][nt][i] -> out[(b*64+o)*HW + h*Wn + px] + bias
#pragma unroll
    for (int nt = 0; nt < 8; ++nt) {
        int o0 = nt * 8 + lr * 2;
        float bb0 = __ldg(deform_b + o0);
        float bb1 = __ldg(deform_b + o0 + 1);
#pragma unroll
        for (int mt = 0; mt < 2; ++mt) {
            int px0 = wrp * 32 + mt * 16 + lq;
            float* o0p = out + ((size_t)(b * On + o0)) * HW + h * Wn;
            float* o1p = o0p + HW;
            o0p[px0]     = d[mt][nt][0] + bb0;
            o1p[px0]     = d[mt][nt][1] + bb1;
            o0p[px0 + 8] = d[mt][nt][2] + bb0;
            o1p[px0 + 8] = d[mt][nt][3] + bb1;
        }
    }
}

// ---------------------------------------------------------------------------
extern "C" void kernel_launch(void* const* d_in, const int* in_sizes, int n_in,
                              void* d_out, int out_size) {
    const float* x        = (const float*)d_in[0];
    const float* offset_w = (const float*)d_in[1];
    const float* offset_b = (const float*)d_in[2];
    const float* mask_w   = (const float*)d_in[3];
    const float* mask_b   = (const float*)d_in[4];
    const float* deform_w = (const float*)d_in[5];
    const float* deform_b = (const float*)d_in[6];
    float* out = (float*)d_out;

    int smemA = Cn * 9 * 28 * (int)sizeof(float);   // 64512
    cudaFuncSetAttribute(offset_mask_kernel,
                         cudaFuncAttributeMaxDynamicSharedMemorySize, smemA);
    cudaFuncSetAttribute(deform_kernel,
                         cudaFuncAttributeMaxDynamicSharedMemorySize, S_TOT);

    prep_w_kernel<<<(9 * 64 * 32 + 255) / 256, 256>>>(deform_w);

    dim3 gridA(Hn / 2, Bn);
    offset_mask_kernel<<<gridA, 256, smemA>>>(x, offset_w, offset_b,
                                              mask_w, mask_b);
    dim3 gridB(Hn, Bn);
    deform_kernel<<<gridB, 128, S_TOT>>>(x, deform_b, out);
}